// round 3
// baseline (speedup 1.0000x reference)
#include <cuda_runtime.h>

#define H_IMG 512
#define W_IMG 512
#define NPLANES 96            // 32 * 3
#define TW 32
#define TH 64
#define IW 42                 // TW + 10
#define IH 74                 // TH + 10
#define SS 43                 // staged-input smem row stride (odd -> conflict-free)
#define MS 33                 // intermediate smem row stride (conflict-free)
#define NT 256
#define NBX 16                // 512/32
#define NBY 8                 // 512/64
#define NBLK (NBX * NBY * NPLANES)   // 12288
#define C1F 6.5025f
#define C2F 58.5225f
#define NPIX 25165824.0       // 32*3*512*512

#define SMEM_FLOATS (2 * IH * SS + 5 * IH * MS)

__device__ float g_partials[NBLK];
__device__ unsigned int g_count = 0;

#define W11_INIT {0.00102838f, 0.00759871f, 0.03600077f, 0.10936070f, \
                  0.21300560f, 0.26601180f, 0.21300560f, 0.10936070f, \
                  0.03600077f, 0.00759871f, 0.00102838f}

__global__ void __launch_bounds__(NT, 3) ssim_main(const float* __restrict__ gen,
                                                   const float* __restrict__ ref,
                                                   float* __restrict__ out) {
    extern __shared__ float smem[];
    float* sg  = smem;                 // IH*SS
    float* sr  = sg  + IH * SS;        // IH*SS
    float* m1  = sr  + IH * SS;        // IH*MS
    float* m2  = m1  + IH * MS;
    float* mgg = m2  + IH * MS;
    float* mrr = mgg + IH * MS;
    float* mgr = mrr + IH * MS;

    __shared__ float wsum[8];
    __shared__ double dsum[8];
    __shared__ bool is_last;

    const float W11[11] = W11_INIT;

    const int tid = threadIdx.x;
    const int x0 = blockIdx.x * TW;
    const int y0 = blockIdx.y * TH;
    const size_t pb = (size_t)blockIdx.z * (size_t)(H_IMG * W_IMG);
    const float* gp = gen + pb;
    const float* rp = ref + pb;

    // ---- Stage 0: coalesced load of tile+halo into smem, scale, zero-pad ----
    for (int i = tid; i < IH * IW; i += NT) {
        int r = i / IW;
        int c = i - r * IW;
        int gy = y0 + r - 5;
        int gx = x0 + c - 5;
        float gv = 0.f, rv = 0.f;
        if ((unsigned)gy < (unsigned)H_IMG && (unsigned)gx < (unsigned)W_IMG) {
            int idx = gy * W_IMG + gx;
            gv = fmaf(gp[idx], 0.5f, 0.5f);
            rv = fmaf(rp[idx], 0.5f, 0.5f);
        }
        sg[r * SS + c] = gv;
        sr[r * SS + c] = rv;
    }
    __syncthreads();

    // ---- Stage 1: horizontal conv of 5 fields, 4 output cols per item ----
    // items: 74 rows x 8 col-chunks of 4 = 592
    for (int item = tid; item < IH * 8; item += NT) {
        int r = item >> 3;
        int c0 = (item & 7) << 2;
        const float* sgr = sg + r * SS + c0;
        const float* srr = sr + r * SS + c0;
        const int o = r * MS + c0;

        float a[14], b[14];
#pragma unroll
        for (int t = 0; t < 14; t++) { a[t] = sgr[t]; b[t] = srr[t]; }

        // first moments
        {
            float s1[4] = {0.f, 0.f, 0.f, 0.f};
            float s2[4] = {0.f, 0.f, 0.f, 0.f};
#pragma unroll
            for (int k = 0; k < 11; k++) {
                float wk = W11[k];
#pragma unroll
                for (int j = 0; j < 4; j++) {
                    s1[j] = fmaf(wk, a[k + j], s1[j]);
                    s2[j] = fmaf(wk, b[k + j], s2[j]);
                }
            }
#pragma unroll
            for (int j = 0; j < 4; j++) { m1[o + j] = s1[j]; m2[o + j] = s2[j]; }
        }

        // second moments
        {
            float ab[14];
#pragma unroll
            for (int t = 0; t < 14; t++) ab[t] = a[t] * b[t];
#pragma unroll
            for (int t = 0; t < 14; t++) { a[t] = a[t] * a[t]; b[t] = b[t] * b[t]; }

            float sgg[4] = {0.f, 0.f, 0.f, 0.f};
            float srr2[4] = {0.f, 0.f, 0.f, 0.f};
            float sgr2[4] = {0.f, 0.f, 0.f, 0.f};
#pragma unroll
            for (int k = 0; k < 11; k++) {
                float wk = W11[k];
#pragma unroll
                for (int j = 0; j < 4; j++) {
                    sgg[j]  = fmaf(wk, a[k + j],  sgg[j]);
                    srr2[j] = fmaf(wk, b[k + j],  srr2[j]);
                    sgr2[j] = fmaf(wk, ab[k + j], sgr2[j]);
                }
            }
#pragma unroll
            for (int j = 0; j < 4; j++) {
                mgg[o + j] = sgg[j];
                mrr[o + j] = srr2[j];
                mgr[o + j] = sgr2[j];
            }
        }
    }
    __syncthreads();

    // ---- Stage 2: vertical conv (8 output rows per thread) + SSIM ----
    float lsum = 0.f;
    {
        const int c = tid & 31;
        const int r0 = (tid >> 5) << 3;   // 8 groups * 8 rows = 64

        float o1[8], o2[8], ogg[8], orr[8], ogr[8];

#define VCONV(MARR, OUT)                                                  \
        {                                                                 \
            float v[18];                                                  \
            _Pragma("unroll")                                             \
            for (int t = 0; t < 18; t++) v[t] = MARR[(r0 + t) * MS + c];  \
            _Pragma("unroll")                                             \
            for (int j = 0; j < 8; j++) {                                 \
                float acc = 0.f;                                          \
                _Pragma("unroll")                                         \
                for (int k = 0; k < 11; k++)                              \
                    acc = fmaf(W11[k], v[j + k], acc);                    \
                OUT[j] = acc;                                             \
            }                                                             \
        }
        VCONV(m1,  o1)
        VCONV(m2,  o2)
        VCONV(mgg, ogg)
        VCONV(mrr, orr)
        VCONV(mgr, ogr)
#undef VCONV

#pragma unroll
        for (int j = 0; j < 8; j++) {
            float mu1 = o1[j], mu2 = o2[j];
            float mu1s = mu1 * mu1;
            float mu2s = mu2 * mu2;
            float mu12 = mu1 * mu2;
            float s11 = ogg[j] - mu1s;
            float s22 = orr[j] - mu2s;
            float s12 = ogr[j] - mu12;
            float num = (2.f * mu12 + C1F) * (2.f * s12 + C2F);
            float den = (mu1s + mu2s + C1F) * (s11 + s22 + C2F);
            lsum += __fdividef(num, den);
        }
    }

    // ---- Block reduction (fp32) ----
#pragma unroll
    for (int off = 16; off > 0; off >>= 1)
        lsum += __shfl_xor_sync(0xffffffffu, lsum, off);
    if ((tid & 31) == 0) wsum[tid >> 5] = lsum;
    __syncthreads();

    if (tid == 0) {
        float s = 0.f;
#pragma unroll
        for (int i = 0; i < 8; i++) s += wsum[i];
        int bid = blockIdx.x + NBX * (blockIdx.y + NBY * blockIdx.z);
        g_partials[bid] = s;
        __threadfence();
        unsigned int t = atomicAdd(&g_count, 1u);
        is_last = (t == (unsigned)(NBLK - 1));
    }
    __syncthreads();

    // ---- Last block: deterministic final reduction ----
    if (is_last) {
        __threadfence();
        double acc = 0.0;
        for (int i = tid; i < NBLK; i += NT)
            acc += (double)g_partials[i];
#pragma unroll
        for (int off = 16; off > 0; off >>= 1)
            acc += __shfl_xor_sync(0xffffffffu, acc, off);
        if ((tid & 31) == 0) dsum[tid >> 5] = acc;
        __syncthreads();
        if (tid == 0) {
            double s = 0.0;
#pragma unroll
            for (int i = 0; i < 8; i++) s += dsum[i];
            out[0] = (float)(1.0 - s / NPIX);
            g_count = 0;   // self-reset -> graph-replay deterministic
        }
    }
}

extern "C" void kernel_launch(void* const* d_in, const int* in_sizes, int n_in,
                              void* d_out, int out_size) {
    const float* gen = (const float*)d_in[0];
    const float* ref = (const float*)d_in[1];
    float* out = (float*)d_out;

    size_t shmem = (size_t)SMEM_FLOATS * sizeof(float);   // ~74.3KB
    cudaFuncSetAttribute(ssim_main, cudaFuncAttributeMaxDynamicSharedMemorySize,
                         (int)shmem);

    dim3 grid(NBX, NBY, NPLANES);
    ssim_main<<<grid, NT, shmem>>>(gen, ref, out);
}

// round 4
// speedup vs baseline: 1.5311x; 1.5311x over previous
#include <cuda_runtime.h>

#define H_IMG 512
#define W_IMG 512
#define NPLANES 96            // 32 * 3
#define TW 32
#define TH 64
#define IW 42                 // TW + 10
#define IH 74                 // TH + 10
#define SS 43                 // staged-input smem row stride (odd -> conflict-free)
#define MS 33                 // intermediate smem row stride (conflict-free)
#define NT 256
#define NBX 16                // 512/32
#define NBY 8                 // 512/64
#define NBLK (NBX * NBY * NPLANES)   // 12288
#define C1F 6.5025f
#define C2F 58.5225f
#define NPIX 25165824.0       // 32*3*512*512

// smem: 2 input planes (IH*SS) + 4 intermediate fields (IH*MS)
#define SMEM_FLOATS (2 * IH * SS + 4 * IH * MS)

__device__ float g_partials[NBLK];
__device__ unsigned int g_count = 0;

#define W11_INIT {0.00102838f, 0.00759871f, 0.03600077f, 0.10936070f, \
                  0.21300560f, 0.26601180f, 0.21300560f, 0.10936070f, \
                  0.03600077f, 0.00759871f, 0.00102838f}

__global__ void __launch_bounds__(NT, 3) ssim_main(const float* __restrict__ gen,
                                                   const float* __restrict__ ref,
                                                   float* __restrict__ out) {
    extern __shared__ float smem[];
    float* sg  = smem;                 // IH*SS  staged gen
    float* sr  = sg  + IH * SS;        // IH*SS  staged ref
    float* m1  = sr  + IH * SS;        // IH*MS  conv_h(g)
    float* m2  = m1  + IH * MS;        // IH*MS  conv_h(r)
    float* mss = m2  + IH * MS;        // IH*MS  conv_h(g^2 + r^2)
    float* mgr = mss + IH * MS;        // IH*MS  conv_h(g*r)

    __shared__ float wsum[8];
    __shared__ double dsum[8];
    __shared__ bool is_last;

    const float W11[11] = W11_INIT;

    const int tid = threadIdx.x;
    const int x0 = blockIdx.x * TW;
    const int y0 = blockIdx.y * TH;
    const size_t pb = (size_t)blockIdx.z * (size_t)(H_IMG * W_IMG);
    const float* gp = gen + pb;
    const float* rp = ref + pb;

    // ---- Stage 0: coalesced load of tile+halo into smem, scale, zero-pad ----
    for (int i = tid; i < IH * IW; i += NT) {
        int r = i / IW;
        int c = i - r * IW;
        int gy = y0 + r - 5;
        int gx = x0 + c - 5;
        float gv = 0.f, rv = 0.f;
        if ((unsigned)gy < (unsigned)H_IMG && (unsigned)gx < (unsigned)W_IMG) {
            int idx = gy * W_IMG + gx;
            gv = fmaf(gp[idx], 0.5f, 0.5f);
            rv = fmaf(rp[idx], 0.5f, 0.5f);
        }
        sg[r * SS + c] = gv;
        sr[r * SS + c] = rv;
    }
    __syncthreads();

    // ---- Stage 1: horizontal conv, 4 fields, 4 output cols per item ----
    // items: 74 rows x 8 col-chunks of 4 = 592
    for (int item = tid; item < IH * 8; item += NT) {
        int r = item >> 3;
        int c0 = (item & 7) << 2;
        const float* sgr = sg + r * SS + c0;
        const float* srr = sr + r * SS + c0;
        const int o = r * MS + c0;

        float a[14], b[14];
#pragma unroll
        for (int t = 0; t < 14; t++) { a[t] = sgr[t]; b[t] = srr[t]; }

        // first moments (accumulators die at the stores)
        {
            float s1[4] = {0.f, 0.f, 0.f, 0.f};
            float s2[4] = {0.f, 0.f, 0.f, 0.f};
#pragma unroll
            for (int k = 0; k < 11; k++) {
                float wk = W11[k];
#pragma unroll
                for (int j = 0; j < 4; j++) {
                    s1[j] = fmaf(wk, a[k + j], s1[j]);
                    s2[j] = fmaf(wk, b[k + j], s2[j]);
                }
            }
#pragma unroll
            for (int j = 0; j < 4; j++) { m1[o + j] = s1[j]; m2[o + j] = s2[j]; }
        }

        // in-place transform: a <- g^2 + r^2,  b <- g*r
#pragma unroll
        for (int t = 0; t < 14; t++) {
            float pa = a[t];
            float pb = b[t];
            a[t] = fmaf(pa, pa, pb * pb);
            b[t] = pa * pb;
        }

        // second moments
        {
            float s3[4] = {0.f, 0.f, 0.f, 0.f};
            float s4[4] = {0.f, 0.f, 0.f, 0.f};
#pragma unroll
            for (int k = 0; k < 11; k++) {
                float wk = W11[k];
#pragma unroll
                for (int j = 0; j < 4; j++) {
                    s3[j] = fmaf(wk, a[k + j], s3[j]);
                    s4[j] = fmaf(wk, b[k + j], s4[j]);
                }
            }
#pragma unroll
            for (int j = 0; j < 4; j++) { mss[o + j] = s3[j]; mgr[o + j] = s4[j]; }
        }
    }
    __syncthreads();

    // ---- Stage 2: vertical conv (8 rows/thread), streaming SSIM combine ----
    float lsum = 0.f;
    {
        const int c = tid & 31;
        const int r0 = (tid >> 5) << 3;   // 8 groups * 8 rows = 64

#define VCONV(MARR, OUT)                                                  \
        {                                                                 \
            float v[18];                                                  \
            _Pragma("unroll")                                             \
            for (int t = 0; t < 18; t++) v[t] = MARR[(r0 + t) * MS + c];  \
            _Pragma("unroll")                                             \
            for (int j = 0; j < 8; j++) {                                 \
                float acc = 0.f;                                          \
                _Pragma("unroll")                                         \
                for (int k = 0; k < 11; k++)                              \
                    acc = fmaf(W11[k], v[j + k], acc);                    \
                OUT[j] = acc;                                             \
            }                                                             \
        }

        float q[8];    // mu1^2 + mu2^2
        float p[8];    // mu1 * mu2
        {
            float o1[8], o2[8];
            VCONV(m1, o1)
            VCONV(m2, o2)
#pragma unroll
            for (int j = 0; j < 8; j++) {
                q[j] = fmaf(o1[j], o1[j], o2[j] * o2[j]);
                p[j] = o1[j] * o2[j];
            }
        }

        float dden[8];   // (q + C1) * (oss - q + C2)
        {
            float oss[8];
            VCONV(mss, oss)
#pragma unroll
            for (int j = 0; j < 8; j++)
                dden[j] = (q[j] + C1F) * (oss[j] - q[j] + C2F);
        }

        {
            float ogr[8];
            VCONV(mgr, ogr)
#pragma unroll
            for (int j = 0; j < 8; j++) {
                float num = fmaf(2.f, p[j], C1F) *
                            fmaf(2.f, ogr[j] - p[j], C2F);
                lsum += __fdividef(num, dden[j]);
            }
        }
#undef VCONV
    }

    // ---- Block reduction (fp32) ----
#pragma unroll
    for (int off = 16; off > 0; off >>= 1)
        lsum += __shfl_xor_sync(0xffffffffu, lsum, off);
    if ((tid & 31) == 0) wsum[tid >> 5] = lsum;
    __syncthreads();

    if (tid == 0) {
        float s = 0.f;
#pragma unroll
        for (int i = 0; i < 8; i++) s += wsum[i];
        int bid = blockIdx.x + NBX * (blockIdx.y + NBY * blockIdx.z);
        g_partials[bid] = s;
        __threadfence();
        unsigned int t = atomicAdd(&g_count, 1u);
        is_last = (t == (unsigned)(NBLK - 1));
    }
    __syncthreads();

    // ---- Last block: deterministic final reduction ----
    if (is_last) {
        __threadfence();
        double acc = 0.0;
        for (int i = tid; i < NBLK; i += NT)
            acc += (double)g_partials[i];
#pragma unroll
        for (int off = 16; off > 0; off >>= 1)
            acc += __shfl_xor_sync(0xffffffffu, acc, off);
        if ((tid & 31) == 0) dsum[tid >> 5] = acc;
        __syncthreads();
        if (tid == 0) {
            double s = 0.0;
#pragma unroll
            for (int i = 0; i < 8; i++) s += dsum[i];
            out[0] = (float)(1.0 - s / NPIX);
            g_count = 0;   // self-reset -> graph-replay deterministic
        }
    }
}

extern "C" void kernel_launch(void* const* d_in, const int* in_sizes, int n_in,
                              void* d_out, int out_size) {
    const float* gen = (const float*)d_in[0];
    const float* ref = (const float*)d_in[1];
    float* out = (float*)d_out;

    size_t shmem = (size_t)SMEM_FLOATS * sizeof(float);   // ~64.5KB
    cudaFuncSetAttribute(ssim_main, cudaFuncAttributeMaxDynamicSharedMemorySize,
                         (int)shmem);

    dim3 grid(NBX, NBY, NPLANES);
    ssim_main<<<grid, NT, shmem>>>(gen, ref, out);
}